// round 3
// baseline (speedup 1.0000x reference)
#include <cuda_runtime.h>

// Problem constants (LSTMLanguageModel: V=128, D=1024, H=1024, L=2, B=64, T=512)
#define VV 128
#define DD 1024
#define HH 1024
#define BB 64
#define TT 512
#define G4 4096          // 4*H gate width

#define KT 16            // K-tile depth
#define SPITCH 68        // smem pitch (floats), 68*4B = 272B = 16B-aligned, conflict-light

// ---------------- device scratch (static: no allocations allowed) ----------------
__device__ float g_Eproj[VV * G4];          // embed @ Wx0^T + b0, per vocab id (2 MB)
__device__ float g_h0[2][BB * HH];          // double-buffered layer0 hidden
__device__ float g_h1[2][BB * HH];          // double-buffered layer1 hidden
__device__ float g_outs[(size_t)BB * TT * HH]; // top-layer h for all t (128 MB)
__device__ unsigned g_count = 0;            // grid barrier
__device__ unsigned g_gen = 0;

// ---------------- math helpers ----------------
__device__ __forceinline__ float sigf(float x) { return 1.0f / (1.0f + __expf(-x)); }
__device__ __forceinline__ float tanhe(float x) { return 1.0f - 2.0f / (__expf(2.0f * x) + 1.0f); }

// ---------------- software grid barrier (all blocks co-resident: grid <= 148) ----
__device__ __forceinline__ void grid_barrier() {
    __threadfence();
    __syncthreads();
    if (threadIdx.x == 0) {
        unsigned nb = gridDim.x;
        volatile unsigned* vg = &g_gen;
        unsigned my = *vg;
        if (atomicAdd(&g_count, 1u) == nb - 1u) {
            g_count = 0u;
            __threadfence();
            *vg = my + 1u;
        } else {
            while (*vg == my) { }
        }
        __threadfence();
    }
    __syncthreads();
}

// ---------------- 64x64 fp32 tile-GEMM, accumulate into acc[4][4] ----------------
// A: 64 x (nk*16) tile, row stride 1024 floats. Wrow: this thread's weight row
// (row for output column c = tid>>2), advanced by k. Double-buffered smem,
// one __syncthreads per K-tile, global loads overlapped with compute.
__device__ __forceinline__ void gemm_tile(
    const float* __restrict__ A,
    const float* __restrict__ Wrow,
    float* sA, float* sW,            // each 2*KT*SPITCH floats
    float acc[4][4], int tid, int nk)
{
    const int m  = tid >> 2;              // 0..63 (A row / W output col)
    const int kq = (tid & 3) << 2;        // 0,4,8,12
    const int ty = (tid >> 4) << 2;       // output row base
    const int tx = (tid & 15) << 2;       // output col base

    float4 a4 = __ldcg(reinterpret_cast<const float4*>(A + m * 1024 + kq));
    float4 w4 = __ldg(reinterpret_cast<const float4*>(Wrow + kq));

    for (int t = 0; t < nk; ++t) {
        float* cA = sA + (t & 1) * (KT * SPITCH);
        float* cW = sW + (t & 1) * (KT * SPITCH);
        cA[(kq + 0) * SPITCH + m] = a4.x;
        cA[(kq + 1) * SPITCH + m] = a4.y;
        cA[(kq + 2) * SPITCH + m] = a4.z;
        cA[(kq + 3) * SPITCH + m] = a4.w;
        cW[(kq + 0) * SPITCH + m] = w4.x;
        cW[(kq + 1) * SPITCH + m] = w4.y;
        cW[(kq + 2) * SPITCH + m] = w4.z;
        cW[(kq + 3) * SPITCH + m] = w4.w;
        __syncthreads();
        if (t + 1 < nk) {
            int k0 = (t + 1) * KT;
            a4 = __ldcg(reinterpret_cast<const float4*>(A + m * 1024 + k0 + kq));
            w4 = __ldg(reinterpret_cast<const float4*>(Wrow + k0 + kq));
        }
        #pragma unroll
        for (int k = 0; k < KT; ++k) {
            float4 av = *reinterpret_cast<const float4*>(cA + k * SPITCH + ty);
            float4 wv = *reinterpret_cast<const float4*>(cW + k * SPITCH + tx);
            float aa[4] = { av.x, av.y, av.z, av.w };
            float ww[4] = { wv.x, wv.y, wv.z, wv.w };
            #pragma unroll
            for (int i = 0; i < 4; i++)
                #pragma unroll
                for (int j = 0; j < 4; j++)
                    acc[i][j] = fmaf(aa[i], ww[j], acc[i][j]);
        }
        __syncthreads();
    }
}

// ---------------- kernel 1: Eproj[v, g] = embed[v] @ Wx0^T + b0 ----------------
// grid (64 col-tiles, 2 row-tiles), 256 threads
__global__ void __launch_bounds__(256) eproj_kernel(
    const float* __restrict__ embed, const float* __restrict__ Wx,
    const float* __restrict__ b)
{
    __shared__ float sA[2 * KT * SPITCH];
    __shared__ float sW[2 * KT * SPITCH];
    int tid = threadIdx.x;
    int colbase = blockIdx.x * 64;
    int rowbase = blockIdx.y * 64;
    const float* wr = Wx + (size_t)(colbase + (tid >> 2)) * DD;

    float acc[4][4];
    #pragma unroll
    for (int i = 0; i < 4; i++)
        #pragma unroll
        for (int j = 0; j < 4; j++) acc[i][j] = 0.f;

    gemm_tile(embed + (size_t)rowbase * DD, wr, sA, sW, acc, tid, DD / KT);

    int ty = (tid >> 4) << 2, tx = (tid & 15) << 2;
    #pragma unroll
    for (int i = 0; i < 4; i++)
        #pragma unroll
        for (int j = 0; j < 4; j++)
            g_Eproj[(size_t)(rowbase + ty + i) * G4 + colbase + tx + j] =
                acc[i][j] + b[colbase + tx + j];
}

// ---------------- kernel 2: persistent LSTM recurrence ----------------
// 128 blocks x 256 threads; blocks 0..63: layer1 (step t), blocks 64..127:
// layer0 (step t+1). Each block owns 16 hidden columns of its layer (all four
// gates at q*1024 + col), so c-state lives in registers across all 512 steps.
__global__ void __launch_bounds__(256) lstm_kernel(
    const int* __restrict__ x, const float* __restrict__ Wx,
    const float* __restrict__ Wh, const float* __restrict__ b)
{
    __shared__ float sA[2 * KT * SPITCH];
    __shared__ float sW[2 * KT * SPITCH];
    __shared__ float Gs[64 * 65];

    int tid = threadIdx.x;
    int bid = blockIdx.x;
    bool l1 = (bid < 64);
    int col0 = (l1 ? bid : bid - 64) * 16;
    int c = tid >> 2;
    int gr = (c >> 4) * 1024 + col0 + (c & 15);   // weight row for output col c

    const float* wx1 = Wx + (size_t)G4 * DD + (size_t)gr * DD;  // layer1 Wx row
    const float* wh1 = Wh + (size_t)G4 * HH + (size_t)gr * HH;  // layer1 Wh row
    const float* wh0 = Wh + (size_t)gr * HH;                    // layer0 Wh row

    float creg[4] = { 0.f, 0.f, 0.f, 0.f };   // this thread's 4 c-state elements
    int ty = (tid >> 4) << 2, tx = (tid & 15) << 2;

    // ---- prologue (t = 0 for layer0; zero-init h1(-1)) ----
    if (!l1) {
        #pragma unroll
        for (int s = 0; s < 4; s++) {
            int e = s * 256 + tid;
            int bb = e >> 4, j = e & 15;
            int hcol = col0 + j;
            int tok = x[bb * TT + 0];
            const float* ep = g_Eproj + (size_t)tok * G4;
            float gi = ep[hcol];
            float gg = ep[2048 + hcol];
            float go = ep[3072 + hcol];
            float cn = sigf(gi) * tanhe(gg);          // c_prev = 0
            creg[s] = cn;
            g_h0[0][bb * HH + hcol] = sigf(go) * tanhe(cn);
        }
    } else {
        #pragma unroll
        for (int s = 0; s < 4; s++) {
            int e = s * 256 + tid;
            int bb = e >> 4, j = e & 15;
            g_h1[1][bb * HH + col0 + j] = 0.f;        // h1(-1) = 0 (parity 1)
        }
    }
    grid_barrier();

    // ---- main loop: phase t computes layer1(t) and layer0(t+1) ----
    for (int t = 0; t < TT; ++t) {
        float acc[4][4];
        #pragma unroll
        for (int i = 0; i < 4; i++)
            #pragma unroll
            for (int j = 0; j < 4; j++) acc[i][j] = 0.f;

        if (l1) {
            // gates1(t) = h0(t) @ Wx1^T + h1(t-1) @ Wh1^T  (+ b1 later)
            gemm_tile(g_h0[t & 1], wx1, sA, sW, acc, tid, HH / KT);
            gemm_tile(g_h1[(t & 1) ^ 1], wh1, sA, sW, acc, tid, HH / KT);
            #pragma unroll
            for (int i = 0; i < 4; i++)
                #pragma unroll
                for (int j = 0; j < 4; j++)
                    Gs[(ty + i) * 65 + tx + j] = acc[i][j];
            __syncthreads();
            #pragma unroll
            for (int s = 0; s < 4; s++) {
                int e = s * 256 + tid;
                int bb = e >> 4, j = e & 15;
                int hcol = col0 + j;
                float gi = Gs[bb * 65 + j]      + b[G4 + hcol];
                float gf = Gs[bb * 65 + 16 + j] + b[G4 + 1024 + hcol];
                float gg = Gs[bb * 65 + 32 + j] + b[G4 + 2048 + hcol];
                float go = Gs[bb * 65 + 48 + j] + b[G4 + 3072 + hcol];
                float cn = sigf(gf) * creg[s] + sigf(gi) * tanhe(gg);
                creg[s] = cn;
                float h = sigf(go) * tanhe(cn);
                g_h1[t & 1][bb * HH + hcol] = h;
                g_outs[(size_t)(bb * TT + t) * HH + hcol] = h;
            }
        } else if (t < TT - 1) {
            // gates0(t+1) = Eproj[x[:,t+1]] + h0(t) @ Wh0^T
            gemm_tile(g_h0[t & 1], wh0, sA, sW, acc, tid, HH / KT);
            #pragma unroll
            for (int i = 0; i < 4; i++)
                #pragma unroll
                for (int j = 0; j < 4; j++)
                    Gs[(ty + i) * 65 + tx + j] = acc[i][j];
            __syncthreads();
            #pragma unroll
            for (int s = 0; s < 4; s++) {
                int e = s * 256 + tid;
                int bb = e >> 4, j = e & 15;
                int hcol = col0 + j;
                int tok = x[bb * TT + (t + 1)];
                const float* ep = g_Eproj + (size_t)tok * G4;
                float gi = Gs[bb * 65 + j]      + ep[hcol];
                float gf = Gs[bb * 65 + 16 + j] + ep[1024 + hcol];
                float gg = Gs[bb * 65 + 32 + j] + ep[2048 + hcol];
                float go = Gs[bb * 65 + 48 + j] + ep[3072 + hcol];
                float cn = sigf(gf) * creg[s] + sigf(gi) * tanhe(gg);
                creg[s] = cn;
                float h = sigf(go) * tanhe(cn);
                g_h0[(t + 1) & 1][bb * HH + hcol] = h;
            }
        }
        grid_barrier();
    }
}

// ---------------- kernel 3: logits = outs @ Wout^T + bout ----------------
// grid (512 row-tiles, 2 col-tiles)
__global__ void __launch_bounds__(256) proj_kernel(
    const float* __restrict__ Wout, const float* __restrict__ bout,
    float* __restrict__ out)
{
    __shared__ float sA[2 * KT * SPITCH];
    __shared__ float sW[2 * KT * SPITCH];
    int tid = threadIdx.x;
    int rowbase = blockIdx.x * 64;
    int colbase = blockIdx.y * 64;
    const float* wr = Wout + (size_t)(colbase + (tid >> 2)) * HH;

    float acc[4][4];
    #pragma unroll
    for (int i = 0; i < 4; i++)
        #pragma unroll
        for (int j = 0; j < 4; j++) acc[i][j] = 0.f;

    gemm_tile(g_outs + (size_t)rowbase * HH, wr, sA, sW, acc, tid, HH / KT);

    int ty = (tid >> 4) << 2, tx = (tid & 15) << 2;
    #pragma unroll
    for (int i = 0; i < 4; i++)
        #pragma unroll
        for (int j = 0; j < 4; j++)
            out[(size_t)(rowbase + ty + i) * VV + colbase + tx + j] =
                acc[i][j] + bout[colbase + tx + j];
}

// ---------------- launch ----------------
extern "C" void kernel_launch(void* const* d_in, const int* in_sizes, int n_in,
                              void* d_out, int out_size) {
    const int*   x     = (const int*)d_in[0];    // [64,512] int32
    const float* embed = (const float*)d_in[1];  // [128,1024]
    const float* Wx    = (const float*)d_in[2];  // [2,4096,1024]
    const float* Wh    = (const float*)d_in[3];  // [2,4096,1024]
    const float* b     = (const float*)d_in[4];  // [2,4096]
    const float* Wout  = (const float*)d_in[5];  // [128,1024]
    const float* bout  = (const float*)d_in[6];  // [128]
    float* out = (float*)d_out;                  // [64,512,128]

    (void)in_sizes; (void)n_in; (void)out_size;

    eproj_kernel<<<dim3(64, 2), 256>>>(embed, Wx, b);
    lstm_kernel<<<128, 256>>>(x, Wx, Wh, b);
    proj_kernel<<<dim3(512, 2), 256>>>(Wout, bout, out);
}

// round 4
// speedup vs baseline: 1.0043x; 1.0043x over previous
#include <cuda_runtime.h>

// Problem constants (LSTMLanguageModel: V=128, D=1024, H=1024, L=2, B=64, T=512)
#define VV 128
#define DD 1024
#define HH 1024
#define BB 64
#define TT 512
#define G4 4096          // 4*H gate width

#define KT 16            // K-tile depth
#define SPITCH 68        // smem pitch (floats), 68*4B = 272B = 16B-aligned, conflict-light

// ---------------- device scratch (static: no allocations allowed) ----------------
__device__ float g_Eproj[VV * G4];          // embed @ Wx0^T + b0, per vocab id (2 MB)
__device__ float g_h0[2][BB * HH];          // double-buffered layer0 hidden
__device__ float g_h1[2][BB * HH];          // double-buffered layer1 hidden
__device__ float g_outs[(size_t)BB * TT * HH]; // top-layer h for all t (128 MB)
__device__ unsigned g_count = 0;            // grid barrier
__device__ unsigned g_gen = 0;

// ---------------- math helpers ----------------
__device__ __forceinline__ float sigf(float x) { return 1.0f / (1.0f + __expf(-x)); }
__device__ __forceinline__ float tanhe(float x) { return 1.0f - 2.0f / (__expf(2.0f * x) + 1.0f); }

// ---------------- software grid barrier (all blocks co-resident: grid <= 148) ----
__device__ __forceinline__ void grid_barrier() {
    __threadfence();
    __syncthreads();
    if (threadIdx.x == 0) {
        unsigned nb = gridDim.x;
        volatile unsigned* vg = &g_gen;
        unsigned my = *vg;
        if (atomicAdd(&g_count, 1u) == nb - 1u) {
            g_count = 0u;
            __threadfence();
            *vg = my + 1u;
        } else {
            while (*vg == my) { }
        }
        __threadfence();
    }
    __syncthreads();
}

// ---------------- 64x64 fp32 tile-GEMM, accumulate into acc[4][4] ----------------
// A: 64 x (nk*16) tile, row stride 1024 floats. Wrow: this thread's weight row
// (row for output column c = tid>>2), advanced by k. Double-buffered smem,
// one __syncthreads per K-tile, global loads overlapped with compute.
__device__ __forceinline__ void gemm_tile(
    const float* __restrict__ A,
    const float* __restrict__ Wrow,
    float* sA, float* sW,            // each 2*KT*SPITCH floats
    float acc[4][4], int tid, int nk)
{
    const int m  = tid >> 2;              // 0..63 (A row / W output col)
    const int kq = (tid & 3) << 2;        // 0,4,8,12
    const int ty = (tid >> 4) << 2;       // output row base
    const int tx = (tid & 15) << 2;       // output col base

    float4 a4 = __ldcg(reinterpret_cast<const float4*>(A + m * 1024 + kq));
    float4 w4 = __ldg(reinterpret_cast<const float4*>(Wrow + kq));

    for (int t = 0; t < nk; ++t) {
        float* cA = sA + (t & 1) * (KT * SPITCH);
        float* cW = sW + (t & 1) * (KT * SPITCH);
        cA[(kq + 0) * SPITCH + m] = a4.x;
        cA[(kq + 1) * SPITCH + m] = a4.y;
        cA[(kq + 2) * SPITCH + m] = a4.z;
        cA[(kq + 3) * SPITCH + m] = a4.w;
        cW[(kq + 0) * SPITCH + m] = w4.x;
        cW[(kq + 1) * SPITCH + m] = w4.y;
        cW[(kq + 2) * SPITCH + m] = w4.z;
        cW[(kq + 3) * SPITCH + m] = w4.w;
        __syncthreads();
        if (t + 1 < nk) {
            int k0 = (t + 1) * KT;
            a4 = __ldcg(reinterpret_cast<const float4*>(A + m * 1024 + k0 + kq));
            w4 = __ldg(reinterpret_cast<const float4*>(Wrow + k0 + kq));
        }
        #pragma unroll
        for (int k = 0; k < KT; ++k) {
            float4 av = *reinterpret_cast<const float4*>(cA + k * SPITCH + ty);
            float4 wv = *reinterpret_cast<const float4*>(cW + k * SPITCH + tx);
            float aa[4] = { av.x, av.y, av.z, av.w };
            float ww[4] = { wv.x, wv.y, wv.z, wv.w };
            #pragma unroll
            for (int i = 0; i < 4; i++)
                #pragma unroll
                for (int j = 0; j < 4; j++)
                    acc[i][j] = fmaf(aa[i], ww[j], acc[i][j]);
        }
        __syncthreads();
    }
}

// ---------------- kernel 1: Eproj[v, g] = embed[v] @ Wx0^T + b0 ----------------
// grid (64 col-tiles, 2 row-tiles), 256 threads
__global__ void __launch_bounds__(256) eproj_kernel(
    const float* __restrict__ embed, const float* __restrict__ Wx,
    const float* __restrict__ b)
{
    __shared__ float sA[2 * KT * SPITCH];
    __shared__ float sW[2 * KT * SPITCH];
    int tid = threadIdx.x;
    int colbase = blockIdx.x * 64;
    int rowbase = blockIdx.y * 64;
    const float* wr = Wx + (size_t)(colbase + (tid >> 2)) * DD;

    float acc[4][4];
    #pragma unroll
    for (int i = 0; i < 4; i++)
        #pragma unroll
        for (int j = 0; j < 4; j++) acc[i][j] = 0.f;

    gemm_tile(embed + (size_t)rowbase * DD, wr, sA, sW, acc, tid, DD / KT);

    int ty = (tid >> 4) << 2, tx = (tid & 15) << 2;
    #pragma unroll
    for (int i = 0; i < 4; i++)
        #pragma unroll
        for (int j = 0; j < 4; j++)
            g_Eproj[(size_t)(rowbase + ty + i) * G4 + colbase + tx + j] =
                acc[i][j] + b[colbase + tx + j];
}

// ---------------- kernel 2: persistent LSTM recurrence ----------------
// 128 blocks x 256 threads; blocks 0..63: layer1 (step t), blocks 64..127:
// layer0 (step t+1). Each block owns 16 hidden columns of its layer (all four
// gates at q*1024 + col), so c-state lives in registers across all 512 steps.
__global__ void __launch_bounds__(256) lstm_kernel(
    const int* __restrict__ x, const float* __restrict__ Wx,
    const float* __restrict__ Wh, const float* __restrict__ b)
{
    __shared__ float sA[2 * KT * SPITCH];
    __shared__ float sW[2 * KT * SPITCH];
    __shared__ float Gs[64 * 65];

    int tid = threadIdx.x;
    int bid = blockIdx.x;
    bool l1 = (bid < 64);
    int col0 = (l1 ? bid : bid - 64) * 16;
    int c = tid >> 2;
    int gr = (c >> 4) * 1024 + col0 + (c & 15);   // weight row for output col c

    const float* wx1 = Wx + (size_t)G4 * DD + (size_t)gr * DD;  // layer1 Wx row
    const float* wh1 = Wh + (size_t)G4 * HH + (size_t)gr * HH;  // layer1 Wh row
    const float* wh0 = Wh + (size_t)gr * HH;                    // layer0 Wh row

    float creg[4] = { 0.f, 0.f, 0.f, 0.f };   // this thread's 4 c-state elements
    int ty = (tid >> 4) << 2, tx = (tid & 15) << 2;

    // ---- prologue (t = 0 for layer0; zero-init h1(-1)) ----
    if (!l1) {
        #pragma unroll
        for (int s = 0; s < 4; s++) {
            int e = s * 256 + tid;
            int bb = e >> 4, j = e & 15;
            int hcol = col0 + j;
            int tok = x[bb * TT + 0];
            const float* ep = g_Eproj + (size_t)tok * G4;
            float gi = ep[hcol];
            float gg = ep[2048 + hcol];
            float go = ep[3072 + hcol];
            float cn = sigf(gi) * tanhe(gg);          // c_prev = 0
            creg[s] = cn;
            g_h0[0][bb * HH + hcol] = sigf(go) * tanhe(cn);
        }
    } else {
        #pragma unroll
        for (int s = 0; s < 4; s++) {
            int e = s * 256 + tid;
            int bb = e >> 4, j = e & 15;
            g_h1[1][bb * HH + col0 + j] = 0.f;        // h1(-1) = 0 (parity 1)
        }
    }
    grid_barrier();

    // ---- main loop: phase t computes layer1(t) and layer0(t+1) ----
    for (int t = 0; t < TT; ++t) {
        float acc[4][4];
        #pragma unroll
        for (int i = 0; i < 4; i++)
            #pragma unroll
            for (int j = 0; j < 4; j++) acc[i][j] = 0.f;

        if (l1) {
            // gates1(t) = h0(t) @ Wx1^T + h1(t-1) @ Wh1^T  (+ b1 later)
            gemm_tile(g_h0[t & 1], wx1, sA, sW, acc, tid, HH / KT);
            gemm_tile(g_h1[(t & 1) ^ 1], wh1, sA, sW, acc, tid, HH / KT);
            #pragma unroll
            for (int i = 0; i < 4; i++)
                #pragma unroll
                for (int j = 0; j < 4; j++)
                    Gs[(ty + i) * 65 + tx + j] = acc[i][j];
            __syncthreads();
            #pragma unroll
            for (int s = 0; s < 4; s++) {
                int e = s * 256 + tid;
                int bb = e >> 4, j = e & 15;
                int hcol = col0 + j;
                float gi = Gs[bb * 65 + j]      + b[G4 + hcol];
                float gf = Gs[bb * 65 + 16 + j] + b[G4 + 1024 + hcol];
                float gg = Gs[bb * 65 + 32 + j] + b[G4 + 2048 + hcol];
                float go = Gs[bb * 65 + 48 + j] + b[G4 + 3072 + hcol];
                float cn = sigf(gf) * creg[s] + sigf(gi) * tanhe(gg);
                creg[s] = cn;
                float h = sigf(go) * tanhe(cn);
                g_h1[t & 1][bb * HH + hcol] = h;
                g_outs[(size_t)(bb * TT + t) * HH + hcol] = h;
            }
        } else if (t < TT - 1) {
            // gates0(t+1) = Eproj[x[:,t+1]] + h0(t) @ Wh0^T
            gemm_tile(g_h0[t & 1], wh0, sA, sW, acc, tid, HH / KT);
            #pragma unroll
            for (int i = 0; i < 4; i++)
                #pragma unroll
                for (int j = 0; j < 4; j++)
                    Gs[(ty + i) * 65 + tx + j] = acc[i][j];
            __syncthreads();
            #pragma unroll
            for (int s = 0; s < 4; s++) {
                int e = s * 256 + tid;
                int bb = e >> 4, j = e & 15;
                int hcol = col0 + j;
                int tok = x[bb * TT + (t + 1)];
                const float* ep = g_Eproj + (size_t)tok * G4;
                float gi = Gs[bb * 65 + j]      + ep[hcol];
                float gf = Gs[bb * 65 + 16 + j] + ep[1024 + hcol];
                float gg = Gs[bb * 65 + 32 + j] + ep[2048 + hcol];
                float go = Gs[bb * 65 + 48 + j] + ep[3072 + hcol];
                float cn = sigf(gf) * creg[s] + sigf(gi) * tanhe(gg);
                creg[s] = cn;
                float h = sigf(go) * tanhe(cn);
                g_h0[(t + 1) & 1][bb * HH + hcol] = h;
            }
        }
        grid_barrier();
    }
}

// ---------------- kernel 3: logits = outs @ Wout^T + bout ----------------
// grid (512 row-tiles, 2 col-tiles)
__global__ void __launch_bounds__(256) proj_kernel(
    const float* __restrict__ Wout, const float* __restrict__ bout,
    float* __restrict__ out)
{
    __shared__ float sA[2 * KT * SPITCH];
    __shared__ float sW[2 * KT * SPITCH];
    int tid = threadIdx.x;
    int rowbase = blockIdx.x * 64;
    int colbase = blockIdx.y * 64;
    const float* wr = Wout + (size_t)(colbase + (tid >> 2)) * HH;

    float acc[4][4];
    #pragma unroll
    for (int i = 0; i < 4; i++)
        #pragma unroll
        for (int j = 0; j < 4; j++) acc[i][j] = 0.f;

    gemm_tile(g_outs + (size_t)rowbase * HH, wr, sA, sW, acc, tid, HH / KT);

    int ty = (tid >> 4) << 2, tx = (tid & 15) << 2;
    #pragma unroll
    for (int i = 0; i < 4; i++)
        #pragma unroll
        for (int j = 0; j < 4; j++)
            out[(size_t)(rowbase + ty + i) * VV + colbase + tx + j] =
                acc[i][j] + bout[colbase + tx + j];
}

// ---------------- launch ----------------
extern "C" void kernel_launch(void* const* d_in, const int* in_sizes, int n_in,
                              void* d_out, int out_size) {
    const int*   x     = (const int*)d_in[0];    // [64,512] int32
    const float* embed = (const float*)d_in[1];  // [128,1024]
    const float* Wx    = (const float*)d_in[2];  // [2,4096,1024]
    const float* Wh    = (const float*)d_in[3];  // [2,4096,1024]
    const float* b     = (const float*)d_in[4];  // [2,4096]
    const float* Wout  = (const float*)d_in[5];  // [128,1024]
    const float* bout  = (const float*)d_in[6];  // [128]
    float* out = (float*)d_out;                  // [64,512,128]

    (void)in_sizes; (void)n_in; (void)out_size;

    eproj_kernel<<<dim3(64, 2), 256>>>(embed, Wx, b);
    lstm_kernel<<<128, 256>>>(x, Wx, Wh, b);
    proj_kernel<<<dim3(512, 2), 256>>>(Wout, bout, out);
}